// round 13
// baseline (speedup 1.0000x reference)
#include <cuda_runtime.h>
#include <cuda_bf16.h>
#include <math.h>

#define BB   2
#define LL   2048
#define NRES 4096
#define KNB  48
#define NIN  416
#define NOUT 128
#define EPITCH 132
#define NKS  26              // 416 / 16
#define FPITCH 848           // featT row pitch bytes (16*53, ldmatrix conflict-free)

// smem byte offsets
#define SMB_FH  0                            // feat hi: 48 * 848 = 40704
#define SMB_FL  40704                        // feat lo: 40704
#define SMB_XJ  81408                        // 48*15 floats = 2880
#define SMB_XI  84288                        // 16 floats
#define SMB_JN  84352                        // 48 int
#define SMB_OFF 84544                        // 48 int
#define SMB_TOT 84800

typedef unsigned long long ull;

// device scratch (no allocations allowed)
__device__ float g_Xall[NRES * 15];
__device__ int   g_Eidx[NRES * KNB];
// W in mma B-fragment order: idx = (ks*16 + nt)*32 + lane, uint2 = {b0, b1}
__device__ uint2 g_WfHi[NKS * 16 * 32];
__device__ uint2 g_WfLo[NKS * 16 * 32];

__device__ __forceinline__ unsigned smem_u32(const void* p) {
    unsigned a;
    asm("{ .reg .u64 t; cvta.to.shared.u64 t, %1; cvt.u32.u64 %0, t; }"
        : "=r"(a) : "l"(p));
    return a;
}
__device__ __forceinline__ void ldm4(unsigned* r, unsigned addr) {
    asm volatile("ldmatrix.sync.aligned.m8n8.x4.shared.b16 {%0,%1,%2,%3}, [%4];"
        : "=r"(r[0]), "=r"(r[1]), "=r"(r[2]), "=r"(r[3]) : "r"(addr));
}
__device__ __forceinline__ void mma16816(float* d, const unsigned* a, uint2 b) {
    asm volatile("mma.sync.aligned.m16n8k16.row.col.f32.bf16.bf16.f32 "
        "{%0,%1,%2,%3}, {%4,%5,%6,%7}, {%8,%9}, {%0,%1,%2,%3};"
        : "+f"(d[0]), "+f"(d[1]), "+f"(d[2]), "+f"(d[3])
        : "r"(a[0]), "r"(a[1]), "r"(a[2]), "r"(a[3]), "r"(b.x), "r"(b.y));
}
__device__ __forceinline__ unsigned pack_bf16(float v0, float v1) {
    __nv_bfloat16 h0 = __float2bfloat16(v0), h1 = __float2bfloat16(v1);
    return ((unsigned)__bfloat16_as_ushort(h1) << 16) | __bfloat16_as_ushort(h0);
}
__device__ __forceinline__ void split_store(char* bh, char* bl, unsigned off,
                                            float v0, float v1) {
    __nv_bfloat16 h0 = __float2bfloat16(v0), h1 = __float2bfloat16(v1);
    float r0 = v0 - __bfloat162float(h0), r1 = v1 - __bfloat162float(h1);
    *(unsigned*)(bh + off) = ((unsigned)__bfloat16_as_ushort(h1) << 16) | __bfloat16_as_ushort(h0);
    *(unsigned*)(bl + off) = pack_bf16(r0, r1);
}

// ---------------------------------------------------------------------------
// Kernel 0: W -> bf16 hi/lo in mma B-fragment order
// ---------------------------------------------------------------------------
__global__ void prep_w_kernel(const float* __restrict__ W_e) {
    int idx = blockIdx.x * 256 + threadIdx.x;       // 416*32 = 13312 items
    if (idx >= NKS * 16 * 32) return;
    int l = idx & 31, t = idx >> 5;
    int ks = t >> 4, nt = t & 15;
    int g = l >> 2, tg = l & 3;
    int k0 = ks * 16 + 2 * tg, n = nt * 8 + g;
    float v00 = W_e[k0 * 128 + n],       v01 = W_e[(k0 + 1) * 128 + n];
    float v10 = W_e[(k0 + 8) * 128 + n], v11 = W_e[(k0 + 9) * 128 + n];
    __nv_bfloat16 h00 = __float2bfloat16(v00), h01 = __float2bfloat16(v01);
    __nv_bfloat16 h10 = __float2bfloat16(v10), h11 = __float2bfloat16(v11);
    g_WfHi[idx] = make_uint2(
        ((unsigned)__bfloat16_as_ushort(h01) << 16) | __bfloat16_as_ushort(h00),
        ((unsigned)__bfloat16_as_ushort(h11) << 16) | __bfloat16_as_ushort(h10));
    g_WfLo[idx] = make_uint2(
        pack_bf16(v00 - __bfloat162float(h00), v01 - __bfloat162float(h01)),
        pack_bf16(v10 - __bfloat162float(h10), v11 - __bfloat162float(h11)));
}

// ---------------------------------------------------------------------------
// Kernel 1: gather backbone atoms, build virtual atom
// ---------------------------------------------------------------------------
__global__ void build_xall_kernel(const float* __restrict__ X,
                                  const int* __restrict__ S,
                                  const int* __restrict__ table) {
    int g = blockIdx.x * blockDim.x + threadIdx.x;
    if (g >= NRES) return;
    int s = S[g];
    const float* Xr = X + (size_t)g * 14 * 3;
    float bb[12];
#pragma unroll
    for (int a = 0; a < 4; a++) {
        int ai = table[s * 4 + a];
        bb[a * 3 + 0] = Xr[ai * 3 + 0];
        bb[a * 3 + 1] = Xr[ai * 3 + 1];
        bb[a * 3 + 2] = Xr[ai * 3 + 2];
    }
    float b1x = bb[0] - bb[3], b1y = bb[1] - bb[4], b1z = bb[2] - bb[5];
    float b2x = bb[6] - bb[3], b2y = bb[7] - bb[4], b2z = bb[8] - bb[5];
    float nx = b1y * b2z - b1z * b2y;
    float ny = b1z * b2x - b1x * b2z;
    float nz = b1x * b2y - b1y * b2x;
    const float wN = 0.58273431f, w1 = -0.56802827f, w2 = -0.54067466f;
    float vx = wN * nx + w1 * b1x + w2 * b2x + bb[3];
    float vy = wN * ny + w1 * b1y + w2 * b2y + bb[4];
    float vz = wN * nz + w1 * b1z + w2 * b2z + bb[5];
    float* o = g_Xall + g * 15;
#pragma unroll
    for (int t = 0; t < 12; t++) o[t] = bb[t];
    o[12] = vx; o[13] = vy; o[14] = vz;
}

// ---------------------------------------------------------------------------
// Kernel 2: top-48 by 2-level radix select (proven, unchanged)
// ---------------------------------------------------------------------------
__global__ void topk_kernel(float* __restrict__ outEidxF, int write_idx_out) {
    __shared__ unsigned ud[LL];
    __shared__ int      hist[256];
    __shared__ unsigned cand_u[LL];
    __shared__ int      cand_i[LL];
    __shared__ unsigned sel_u[KNB];
    __shared__ int      sel_i[KNB];
    __shared__ int s_E, s_cA, s_M, s_c0, s_nsel, s_ncand;

    int row = blockIdx.x;
    int b = row / LL;
    int tid = threadIdx.x;

    const float* ca_i = g_Xall + row * 15 + 3;
    float cx = ca_i[0], cy = ca_i[1], cz = ca_i[2];
    for (int j = tid; j < LL; j += 256) {
        const float* cj = g_Xall + (b * LL + j) * 15 + 3;
        float dx = cx - cj[0], dy = cy - cj[1], dz = cz - cj[2];
        float d = sqrtf(dx * dx + dy * dy + dz * dz + 1e-6f);
        ud[j] = __float_as_uint(d);
    }
    hist[tid] = 0;
    if (tid == 0) { s_nsel = 0; s_ncand = 0; }
    __syncthreads();

    for (int j = tid; j < LL; j += 256) atomicAdd(&hist[ud[j] >> 23], 1);
    __syncthreads();
    if (tid < 32) {
        int base = tid * 8, loc[8], s = 0;
#pragma unroll
        for (int k = 0; k < 8; k++) { loc[k] = hist[base + k]; s += loc[k]; }
        int pre = s;
#pragma unroll
        for (int o = 1; o < 32; o <<= 1) {
            int v = __shfl_up_sync(0xffffffffu, pre, o);
            if (tid >= o) pre += v;
        }
        int excl = pre - s;
        if (excl < KNB && pre >= KNB) {
            int c = excl;
#pragma unroll
            for (int k = 0; k < 8; k++) {
                if (c + loc[k] >= KNB) { s_E = base + k; s_cA = c; break; }
                c += loc[k];
            }
        }
    }
    __syncthreads();
    int E = s_E, cA = s_cA, target2 = KNB - cA;
    hist[tid] = 0;
    __syncthreads();

    for (int j = tid; j < LL; j += 256) {
        unsigned u = ud[j];
        if ((int)(u >> 23) == E) atomicAdd(&hist[(u >> 15) & 0xFF], 1);
    }
    __syncthreads();
    if (tid < 32) {
        int base = tid * 8, loc[8], s = 0;
#pragma unroll
        for (int k = 0; k < 8; k++) { loc[k] = hist[base + k]; s += loc[k]; }
        int pre = s;
#pragma unroll
        for (int o = 1; o < 32; o <<= 1) {
            int v = __shfl_up_sync(0xffffffffu, pre, o);
            if (tid >= o) pre += v;
        }
        int excl = pre - s;
        if (excl < target2 && pre >= target2) {
            int c = excl;
#pragma unroll
            for (int k = 0; k < 8; k++) {
                if (c + loc[k] >= target2) { s_M = base + k; s_c0 = cA + c; break; }
                c += loc[k];
            }
        }
    }
    __syncthreads();
    unsigned T17 = ((unsigned)E << 8) | (unsigned)s_M;
    int c0 = s_c0;

    for (int j = tid; j < LL; j += 256) {
        unsigned u = ud[j], k17 = u >> 15;
        if (k17 < T17) {
            int p = atomicAdd(&s_nsel, 1);
            sel_u[p] = u; sel_i[p] = j;
        } else if (k17 == T17) {
            int p = atomicAdd(&s_ncand, 1);
            cand_u[p] = u; cand_i[p] = j;
        }
    }
    __syncthreads();

    int need = KNB - c0;
    int s = s_ncand;
    for (int c = tid; c < s; c += 256) {
        unsigned u = cand_u[c]; int i = cand_i[c]; int r = 0;
        for (int c2 = 0; c2 < s; c2++) {
            unsigned u2 = cand_u[c2]; int i2 = cand_i[c2];
            if (u2 < u || (u2 == u && i2 < i)) r++;
        }
        if (r < need) { sel_u[c0 + r] = u; sel_i[c0 + r] = i; }
    }
    __syncthreads();

    for (int t = tid; t < KNB; t += 256) {
        if (t < c0) {
            unsigned u = sel_u[t]; int i = sel_i[t]; int r = 0;
            for (int t2 = 0; t2 < c0; t2++) {
                unsigned u2 = sel_u[t2]; int i2 = sel_i[t2];
                if (u2 < u || (u2 == u && i2 < i)) r++;
            }
            g_Eidx[row * KNB + r] = i;
            if (write_idx_out) outEidxF[(size_t)row * KNB + r] = (float)i;
        } else {
            int i = sel_i[t];
            g_Eidx[row * KNB + t] = i;
            if (write_idx_out) outEidxF[(size_t)row * KNB + t] = (float)i;
        }
    }
}

// ---------------------------------------------------------------------------
// Kernel 3: features (bf16 hi/lo) + mma.sync 3-term GEMM (A-pipelined) + LN.
// 256 threads; warp w owns n-tiles 2w..2w+1 (16 channels).
// ---------------------------------------------------------------------------
__global__ __launch_bounds__(256)
void edge_kernel(const int* __restrict__ residue_idx,
                 const float* __restrict__ W_pos, const float* __restrict__ b_pos,
                 const float* __restrict__ ln_g, const float* __restrict__ ln_b,
                 float* __restrict__ outE) {
    extern __shared__ char smc[];
    float* smf = (float*)smc;
    unsigned smem_base = smem_u32(smc);

    int row = blockIdx.x;
    int b = row / LL;
    int tid = threadIdx.x;
    int wid = tid >> 5, lane = tid & 31;

    char* fh = smc + SMB_FH;
    char* fl = smc + SMB_FL;
    float* xj = (float*)(smc + SMB_XJ);
    float* xi = (float*)(smc + SMB_XI);
    int*   jn = (int*)(smc + SMB_JN);
    int*   offp = (int*)(smc + SMB_OFF);

    if (tid < 15) xi[tid] = g_Xall[row * 15 + tid];
    if (tid < KNB) {
        int j = g_Eidx[row * KNB + tid];
        jn[tid] = j;
        int d = residue_idx[row] - residue_idx[b * LL + j] + 32;
        d = min(max(d, 0), 64);
        offp[tid] = d;
    }
    __syncthreads();
    for (int t = tid; t < KNB * 15; t += 256) {
        int e = t / 15, cmp = t % 15;
        xj[t] = g_Xall[(b * LL + jn[e]) * 15 + cmp];
    }
    __syncthreads();

    // fill featT (bf16 hi/lo), row = edge (pitch 848B), col = feature
    const float inv_sig = 1.0f / 1.25f;
    for (int t = tid; t < KNB * 26; t += 256) {
        int e = t % KNB, g = t / KNB;
        char* rh = fh + e * FPITCH;
        char* rl = fl + e * FPITCH;
        if (g == 0) {
            const float* wp = W_pos + offp[e] * 16;
#pragma unroll
            for (int k2 = 0; k2 < 8; k2++) {
                float v0 = wp[2 * k2] + b_pos[2 * k2];
                float v1 = wp[2 * k2 + 1] + b_pos[2 * k2 + 1];
                split_store(rh, rl, 4 * k2, v0, v1);
            }
        } else {
            int p = g - 1, a = p / 5, cc = p % 5;
            float dx = xi[a * 3 + 0] - xj[e * 15 + cc * 3 + 0];
            float dy = xi[a * 3 + 1] - xj[e * 15 + cc * 3 + 1];
            float dz = xi[a * 3 + 2] - xj[e * 15 + cc * 3 + 2];
            float d = sqrtf(dx * dx + dy * dy + dz * dz + 1e-6f);
            unsigned kb = (unsigned)(16 + p * 16) * 2;
#pragma unroll
            for (int m2 = 0; m2 < 8; m2++) {
                float mu0 = 2.0f + (float)(2 * m2) * (20.0f / 15.0f);
                float mu1 = 2.0f + (float)(2 * m2 + 1) * (20.0f / 15.0f);
                float z0 = (d - mu0) * inv_sig, z1 = (d - mu1) * inv_sig;
                split_store(rh, rl, kb + 4 * m2, __expf(-z0 * z0), __expf(-z1 * z1));
            }
        }
    }
    __syncthreads();

    // ---- mma mainloop, software-pipelined A (double-buffered registers) ----
    int lrow = ((lane >> 3) & 1) * 8 + (lane & 7);
    unsigned aoff = (unsigned)lrow * FPITCH + ((unsigned)(lane >> 4)) * 16;
    unsigned ah_base = smem_base + SMB_FH + aoff;
    unsigned al_base = smem_base + SMB_FL + aoff;

    float acc[3][2][4];
#pragma unroll
    for (int m = 0; m < 3; m++)
#pragma unroll
        for (int j = 0; j < 2; j++)
#pragma unroll
            for (int q = 0; q < 4; q++) acc[m][j][q] = 0.0f;

    const uint2* bH = g_WfHi + (wid * 2) * 32 + lane;
    const uint2* bL = g_WfLo + (wid * 2) * 32 + lane;
    uint2 Bh[2], Bl[2], Bh2[2], Bl2[2];
#pragma unroll
    for (int j = 0; j < 2; j++) { Bh[j] = bH[j * 32]; Bl[j] = bL[j * 32]; }

    unsigned Ah[2][3][4], Al[2][3][4];
#pragma unroll
    for (int m = 0; m < 3; m++) ldm4(Ah[0][m], ah_base + m * (16 * FPITCH));
#pragma unroll
    for (int m = 0; m < 3; m++) ldm4(Al[0][m], al_base + m * (16 * FPITCH));

    for (int ks = 0; ks < NKS; ks++) {
        int cur = ks & 1, nxt = cur ^ 1;
        if (ks < NKS - 1) {
            // prefetch A for ks+1 (consumed next iteration -> latency hidden)
#pragma unroll
            for (int m = 0; m < 3; m++)
                ldm4(Ah[nxt][m], ah_base + m * (16 * FPITCH) + (ks + 1) * 32);
#pragma unroll
            for (int m = 0; m < 3; m++)
                ldm4(Al[nxt][m], al_base + m * (16 * FPITCH) + (ks + 1) * 32);
            // prefetch B for ks+1
#pragma unroll
            for (int j = 0; j < 2; j++) {
                Bh2[j] = bH[(ks + 1) * 512 + j * 32];
                Bl2[j] = bL[(ks + 1) * 512 + j * 32];
            }
        }
#pragma unroll
        for (int m = 0; m < 3; m++) {
#pragma unroll
            for (int j = 0; j < 2; j++) {
                mma16816(acc[m][j], Ah[cur][m], Bh[j]);
                mma16816(acc[m][j], Ah[cur][m], Bl[j]);
                mma16816(acc[m][j], Al[cur][m], Bh[j]);
            }
        }
#pragma unroll
        for (int j = 0; j < 2; j++) { Bh[j] = Bh2[j]; Bl[j] = Bl2[j]; }
    }
    __syncthreads();   // featT dead; reuse as Esh

    // write D frags to Esh[edge][ch]
    float* Esh = smf;  // [48][EPITCH] = 25.3 KB, aliases featT
    int g = lane >> 2, tg = lane & 3;
#pragma unroll
    for (int m = 0; m < 3; m++) {
#pragma unroll
        for (int j = 0; j < 2; j++) {
            int ch = (wid * 2 + j) * 8 + 2 * tg;
            int e0 = m * 16 + g;
            Esh[e0 * EPITCH + ch]            = acc[m][j][0];
            Esh[e0 * EPITCH + ch + 1]        = acc[m][j][1];
            Esh[(e0 + 8) * EPITCH + ch]      = acc[m][j][2];
            Esh[(e0 + 8) * EPITCH + ch + 1]  = acc[m][j][3];
        }
    }
    __syncthreads();

    // LayerNorm: warp w handles edges w*6 .. w*6+5
    for (int e = wid * 6; e < wid * 6 + 6; e++) {
        float v0 = Esh[e * EPITCH + lane];
        float v1 = Esh[e * EPITCH + lane + 32];
        float v2 = Esh[e * EPITCH + lane + 64];
        float v3 = Esh[e * EPITCH + lane + 96];
        float s  = v0 + v1 + v2 + v3;
        float ss = v0 * v0 + v1 * v1 + v2 * v2 + v3 * v3;
#pragma unroll
        for (int o = 16; o > 0; o >>= 1) {
            s  += __shfl_xor_sync(0xffffffffu, s, o);
            ss += __shfl_xor_sync(0xffffffffu, ss, o);
        }
        float mean = s * (1.0f / 128.0f);
        float var  = ss * (1.0f / 128.0f) - mean * mean;
        float rstd = rsqrtf(var + 1e-5f);
        size_t base = ((size_t)row * KNB + e) * 128;
        outE[base + lane]      = (v0 - mean) * rstd * ln_g[lane]      + ln_b[lane];
        outE[base + lane + 32] = (v1 - mean) * rstd * ln_g[lane + 32] + ln_b[lane + 32];
        outE[base + lane + 64] = (v2 - mean) * rstd * ln_g[lane + 64] + ln_b[lane + 64];
        outE[base + lane + 96] = (v3 - mean) * rstd * ln_g[lane + 96] + ln_b[lane + 96];
    }
}

// ---------------------------------------------------------------------------
extern "C" void kernel_launch(void* const* d_in, const int* in_sizes, int n_in,
                              void* d_out, int out_size) {
    const float* X     = (const float*)d_in[0];
    const int*   S     = (const int*)d_in[2];
    const int*   ridx  = (const int*)d_in[3];
    const int*   table = (const int*)d_in[5];
    const float* W_pos = (const float*)d_in[6];
    const float* b_pos = (const float*)d_in[7];
    const float* W_e   = (const float*)d_in[8];
    const float* ln_g  = (const float*)d_in[9];
    const float* ln_b  = (const float*)d_in[10];
    float* out = (float*)d_out;

    const size_t E_elems = (size_t)NRES * KNB * NOUT;
    int write_idx = (out_size >= (int)(E_elems + (size_t)NRES * KNB)) ? 1 : 0;

    build_xall_kernel<<<(NRES + 255) / 256, 256>>>(X, S, table);
    prep_w_kernel<<<(NKS * 16 * 32 + 255) / 256, 256>>>(W_e);
    topk_kernel<<<NRES, 256>>>(out + E_elems, write_idx);

    cudaFuncSetAttribute(edge_kernel, cudaFuncAttributeMaxDynamicSharedMemorySize, SMB_TOT);
    edge_kernel<<<NRES, 256, SMB_TOT>>>(ridx, W_pos, b_pos, ln_g, ln_b, out);
}

// round 15
// speedup vs baseline: 1.8764x; 1.8764x over previous
#include <cuda_runtime.h>
#include <cuda_fp16.h>
#include <math.h>

#define BB   2
#define LL   2048
#define NRES 4096
#define KNB  48
#define NIN  416
#define NOUT 128
#define EPITCH 132
#define NKS  26              // 416 / 16
#define FPITCH 848           // feat row pitch bytes (16*53, ldmatrix conflict-free)

// smem byte offsets
#define SMB_FH  0                            // feat fp16: 48 * 848 = 40704
#define SMB_XJ  40704                        // 48*15 floats = 2880
#define SMB_XI  43584                        // 16 floats
#define SMB_JN  43648                        // 48 int
#define SMB_OFF 43840                        // 48 int
#define SMB_TOT 44032

typedef unsigned long long ull;

// device scratch (no allocations allowed)
__device__ float g_Xall[NRES * 15];
__device__ int   g_Eidx[NRES * KNB];
// W fp16 in mma B-fragment order: idx = (ks*16 + nt)*32 + lane, uint2 = {b0, b1}
__device__ uint2 g_Wf[NKS * 16 * 32];

__device__ __forceinline__ unsigned smem_u32(const void* p) {
    unsigned a;
    asm("{ .reg .u64 t; cvta.to.shared.u64 t, %1; cvt.u32.u64 %0, t; }"
        : "=r"(a) : "l"(p));
    return a;
}
__device__ __forceinline__ void ldm4(unsigned* r, unsigned addr) {
    asm volatile("ldmatrix.sync.aligned.m8n8.x4.shared.b16 {%0,%1,%2,%3}, [%4];"
        : "=r"(r[0]), "=r"(r[1]), "=r"(r[2]), "=r"(r[3]) : "r"(addr));
}
__device__ __forceinline__ void mma16816(float* d, const unsigned* a, uint2 b) {
    asm volatile("mma.sync.aligned.m16n8k16.row.col.f32.f16.f16.f32 "
        "{%0,%1,%2,%3}, {%4,%5,%6,%7}, {%8,%9}, {%0,%1,%2,%3};"
        : "+f"(d[0]), "+f"(d[1]), "+f"(d[2]), "+f"(d[3])
        : "r"(a[0]), "r"(a[1]), "r"(a[2]), "r"(a[3]), "r"(b.x), "r"(b.y));
}
__device__ __forceinline__ unsigned pack_h2(float v0, float v1) {
    __half2 h = __floats2half2_rn(v0, v1);
    return *(unsigned*)&h;
}

// ---------------------------------------------------------------------------
// Kernel 0: W -> fp16 in mma B-fragment order
// ---------------------------------------------------------------------------
__global__ void prep_w_kernel(const float* __restrict__ W_e) {
    int idx = blockIdx.x * 256 + threadIdx.x;       // 13312 items
    if (idx >= NKS * 16 * 32) return;
    int l = idx & 31, t = idx >> 5;
    int ks = t >> 4, nt = t & 15;
    int g = l >> 2, tg = l & 3;
    int k0 = ks * 16 + 2 * tg, n = nt * 8 + g;
    g_Wf[idx] = make_uint2(
        pack_h2(W_e[k0 * 128 + n],       W_e[(k0 + 1) * 128 + n]),
        pack_h2(W_e[(k0 + 8) * 128 + n], W_e[(k0 + 9) * 128 + n]));
}

// ---------------------------------------------------------------------------
// Kernel 1: gather backbone atoms, build virtual atom
// ---------------------------------------------------------------------------
__global__ void build_xall_kernel(const float* __restrict__ X,
                                  const int* __restrict__ S,
                                  const int* __restrict__ table) {
    int g = blockIdx.x * blockDim.x + threadIdx.x;
    if (g >= NRES) return;
    int s = S[g];
    const float* Xr = X + (size_t)g * 14 * 3;
    float bb[12];
#pragma unroll
    for (int a = 0; a < 4; a++) {
        int ai = table[s * 4 + a];
        bb[a * 3 + 0] = Xr[ai * 3 + 0];
        bb[a * 3 + 1] = Xr[ai * 3 + 1];
        bb[a * 3 + 2] = Xr[ai * 3 + 2];
    }
    float b1x = bb[0] - bb[3], b1y = bb[1] - bb[4], b1z = bb[2] - bb[5];
    float b2x = bb[6] - bb[3], b2y = bb[7] - bb[4], b2z = bb[8] - bb[5];
    float nx = b1y * b2z - b1z * b2y;
    float ny = b1z * b2x - b1x * b2z;
    float nz = b1x * b2y - b1y * b2x;
    const float wN = 0.58273431f, w1 = -0.56802827f, w2 = -0.54067466f;
    float vx = wN * nx + w1 * b1x + w2 * b2x + bb[3];
    float vy = wN * ny + w1 * b1y + w2 * b2y + bb[4];
    float vz = wN * nz + w1 * b1z + w2 * b2z + bb[5];
    float* o = g_Xall + g * 15;
#pragma unroll
    for (int t = 0; t < 12; t++) o[t] = bb[t];
    o[12] = vx; o[13] = vy; o[14] = vz;
}

// ---------------------------------------------------------------------------
// Kernel 2: top-48 by 2-level radix select (proven, unchanged)
// ---------------------------------------------------------------------------
__global__ void topk_kernel(float* __restrict__ outEidxF, int write_idx_out) {
    __shared__ unsigned ud[LL];
    __shared__ int      hist[256];
    __shared__ unsigned cand_u[LL];
    __shared__ int      cand_i[LL];
    __shared__ unsigned sel_u[KNB];
    __shared__ int      sel_i[KNB];
    __shared__ int s_E, s_cA, s_M, s_c0, s_nsel, s_ncand;

    int row = blockIdx.x;
    int b = row / LL;
    int tid = threadIdx.x;

    const float* ca_i = g_Xall + row * 15 + 3;
    float cx = ca_i[0], cy = ca_i[1], cz = ca_i[2];
    for (int j = tid; j < LL; j += 256) {
        const float* cj = g_Xall + (b * LL + j) * 15 + 3;
        float dx = cx - cj[0], dy = cy - cj[1], dz = cz - cj[2];
        float d = sqrtf(dx * dx + dy * dy + dz * dz + 1e-6f);
        ud[j] = __float_as_uint(d);
    }
    hist[tid] = 0;
    if (tid == 0) { s_nsel = 0; s_ncand = 0; }
    __syncthreads();

    for (int j = tid; j < LL; j += 256) atomicAdd(&hist[ud[j] >> 23], 1);
    __syncthreads();
    if (tid < 32) {
        int base = tid * 8, loc[8], s = 0;
#pragma unroll
        for (int k = 0; k < 8; k++) { loc[k] = hist[base + k]; s += loc[k]; }
        int pre = s;
#pragma unroll
        for (int o = 1; o < 32; o <<= 1) {
            int v = __shfl_up_sync(0xffffffffu, pre, o);
            if (tid >= o) pre += v;
        }
        int excl = pre - s;
        if (excl < KNB && pre >= KNB) {
            int c = excl;
#pragma unroll
            for (int k = 0; k < 8; k++) {
                if (c + loc[k] >= KNB) { s_E = base + k; s_cA = c; break; }
                c += loc[k];
            }
        }
    }
    __syncthreads();
    int E = s_E, cA = s_cA, target2 = KNB - cA;
    hist[tid] = 0;
    __syncthreads();

    for (int j = tid; j < LL; j += 256) {
        unsigned u = ud[j];
        if ((int)(u >> 23) == E) atomicAdd(&hist[(u >> 15) & 0xFF], 1);
    }
    __syncthreads();
    if (tid < 32) {
        int base = tid * 8, loc[8], s = 0;
#pragma unroll
        for (int k = 0; k < 8; k++) { loc[k] = hist[base + k]; s += loc[k]; }
        int pre = s;
#pragma unroll
        for (int o = 1; o < 32; o <<= 1) {
            int v = __shfl_up_sync(0xffffffffu, pre, o);
            if (tid >= o) pre += v;
        }
        int excl = pre - s;
        if (excl < target2 && pre >= target2) {
            int c = excl;
#pragma unroll
            for (int k = 0; k < 8; k++) {
                if (c + loc[k] >= target2) { s_M = base + k; s_c0 = cA + c; break; }
                c += loc[k];
            }
        }
    }
    __syncthreads();
    unsigned T17 = ((unsigned)E << 8) | (unsigned)s_M;
    int c0 = s_c0;

    for (int j = tid; j < LL; j += 256) {
        unsigned u = ud[j], k17 = u >> 15;
        if (k17 < T17) {
            int p = atomicAdd(&s_nsel, 1);
            sel_u[p] = u; sel_i[p] = j;
        } else if (k17 == T17) {
            int p = atomicAdd(&s_ncand, 1);
            cand_u[p] = u; cand_i[p] = j;
        }
    }
    __syncthreads();

    int need = KNB - c0;
    int s = s_ncand;
    for (int c = tid; c < s; c += 256) {
        unsigned u = cand_u[c]; int i = cand_i[c]; int r = 0;
        for (int c2 = 0; c2 < s; c2++) {
            unsigned u2 = cand_u[c2]; int i2 = cand_i[c2];
            if (u2 < u || (u2 == u && i2 < i)) r++;
        }
        if (r < need) { sel_u[c0 + r] = u; sel_i[c0 + r] = i; }
    }
    __syncthreads();

    for (int t = tid; t < KNB; t += 256) {
        if (t < c0) {
            unsigned u = sel_u[t]; int i = sel_i[t]; int r = 0;
            for (int t2 = 0; t2 < c0; t2++) {
                unsigned u2 = sel_u[t2]; int i2 = sel_i[t2];
                if (u2 < u || (u2 == u && i2 < i)) r++;
            }
            g_Eidx[row * KNB + r] = i;
            if (write_idx_out) outEidxF[(size_t)row * KNB + r] = (float)i;
        } else {
            int i = sel_i[t];
            g_Eidx[row * KNB + t] = i;
            if (write_idx_out) outEidxF[(size_t)row * KNB + t] = (float)i;
        }
    }
}

// ---------------------------------------------------------------------------
// Kernel 3: features (fp16) + mma.sync fp16 GEMM + LN.
// 256 threads; warp w owns n-tiles 2w..2w+1 (16 channels).
// ---------------------------------------------------------------------------
__global__ __launch_bounds__(256, 4)
void edge_kernel(const int* __restrict__ residue_idx,
                 const float* __restrict__ W_pos, const float* __restrict__ b_pos,
                 const float* __restrict__ ln_g, const float* __restrict__ ln_b,
                 float* __restrict__ outE) {
    extern __shared__ char smc[];
    float* smf = (float*)smc;
    unsigned smem_base = smem_u32(smc);

    int row = blockIdx.x;
    int b = row / LL;
    int tid = threadIdx.x;
    int wid = tid >> 5, lane = tid & 31;

    char* fh = smc + SMB_FH;
    float* xj = (float*)(smc + SMB_XJ);
    float* xi = (float*)(smc + SMB_XI);
    int*   jn = (int*)(smc + SMB_JN);
    int*   offp = (int*)(smc + SMB_OFF);

    if (tid < 15) xi[tid] = g_Xall[row * 15 + tid];
    if (tid < KNB) {
        int j = g_Eidx[row * KNB + tid];
        jn[tid] = j;
        int d = residue_idx[row] - residue_idx[b * LL + j] + 32;
        d = min(max(d, 0), 64);
        offp[tid] = d;
    }
    __syncthreads();
    for (int t = tid; t < KNB * 15; t += 256) {
        int e = t / 15, cmp = t % 15;
        xj[t] = g_Xall[(b * LL + jn[e]) * 15 + cmp];
    }
    __syncthreads();

    // fill feat (fp16), row = edge (pitch 848B), col = feature
    // uint index of feature f = f/2; RBF group p spans uints 8+8p .. 15+8p
    const float inv_sig = 1.0f / 1.25f;
    for (int t = tid; t < KNB * 26; t += 256) {
        int e = t % KNB, g = t / KNB;
        unsigned* rh = (unsigned*)(fh + e * FPITCH);
        if (g == 0) {
            const float* wp = W_pos + offp[e] * 16;
#pragma unroll
            for (int k2 = 0; k2 < 8; k2++) {
                rh[k2] = pack_h2(wp[2 * k2] + b_pos[2 * k2],
                                 wp[2 * k2 + 1] + b_pos[2 * k2 + 1]);
            }
        } else {
            int p = g - 1, a = p / 5, cc = p % 5;
            float dx = xi[a * 3 + 0] - xj[e * 15 + cc * 3 + 0];
            float dy = xi[a * 3 + 1] - xj[e * 15 + cc * 3 + 1];
            float dz = xi[a * 3 + 2] - xj[e * 15 + cc * 3 + 2];
            float d = sqrtf(dx * dx + dy * dy + dz * dz + 1e-6f);
            unsigned* dst = rh + 8 + p * 8;   // FIX: 16 features = 8 uints per group
#pragma unroll
            for (int m2 = 0; m2 < 8; m2++) {
                float mu0 = 2.0f + (float)(2 * m2) * (20.0f / 15.0f);
                float mu1 = 2.0f + (float)(2 * m2 + 1) * (20.0f / 15.0f);
                float z0 = (d - mu0) * inv_sig, z1 = (d - mu1) * inv_sig;
                dst[m2] = pack_h2(__expf(-z0 * z0), __expf(-z1 * z1));
            }
        }
    }
    __syncthreads();

    // ---- mma mainloop (single fp16 term) ----
    int lrow = ((lane >> 3) & 1) * 8 + (lane & 7);
    unsigned aoff = (unsigned)lrow * FPITCH + ((unsigned)(lane >> 4)) * 16;
    unsigned ah_base = smem_base + SMB_FH + aoff;

    float acc[3][2][4];
#pragma unroll
    for (int m = 0; m < 3; m++)
#pragma unroll
        for (int j = 0; j < 2; j++)
#pragma unroll
            for (int q = 0; q < 4; q++) acc[m][j][q] = 0.0f;

    const uint2* bW = g_Wf + (wid * 2) * 32 + lane;
    uint2 Bw[2], Bw2[2];
#pragma unroll
    for (int j = 0; j < 2; j++) Bw[j] = bW[j * 32];

    for (int ks = 0; ks < NKS; ks++) {
        if (ks < NKS - 1) {
#pragma unroll
            for (int j = 0; j < 2; j++) Bw2[j] = bW[(ks + 1) * 512 + j * 32];
        }
        unsigned Ah[3][4];
#pragma unroll
        for (int m = 0; m < 3; m++) ldm4(Ah[m], ah_base + m * (16 * FPITCH) + ks * 32);
#pragma unroll
        for (int m = 0; m < 3; m++) {
#pragma unroll
            for (int j = 0; j < 2; j++) mma16816(acc[m][j], Ah[m], Bw[j]);
        }
#pragma unroll
        for (int j = 0; j < 2; j++) Bw[j] = Bw2[j];
    }
    __syncthreads();   // feat dead; reuse as Esh

    // write D frags to Esh[edge][ch]
    float* Esh = smf;  // [48][EPITCH] = 25.3 KB, aliases feat
    int g = lane >> 2, tg = lane & 3;
#pragma unroll
    for (int m = 0; m < 3; m++) {
#pragma unroll
        for (int j = 0; j < 2; j++) {
            int ch = (wid * 2 + j) * 8 + 2 * tg;
            int e0 = m * 16 + g;
            Esh[e0 * EPITCH + ch]            = acc[m][j][0];
            Esh[e0 * EPITCH + ch + 1]        = acc[m][j][1];
            Esh[(e0 + 8) * EPITCH + ch]      = acc[m][j][2];
            Esh[(e0 + 8) * EPITCH + ch + 1]  = acc[m][j][3];
        }
    }
    __syncthreads();

    // LayerNorm: warp w handles edges w*6 .. w*6+5
    for (int e = wid * 6; e < wid * 6 + 6; e++) {
        float v0 = Esh[e * EPITCH + lane];
        float v1 = Esh[e * EPITCH + lane + 32];
        float v2 = Esh[e * EPITCH + lane + 64];
        float v3 = Esh[e * EPITCH + lane + 96];
        float s  = v0 + v1 + v2 + v3;
        float ss = v0 * v0 + v1 * v1 + v2 * v2 + v3 * v3;
#pragma unroll
        for (int o = 16; o > 0; o >>= 1) {
            s  += __shfl_xor_sync(0xffffffffu, s, o);
            ss += __shfl_xor_sync(0xffffffffu, ss, o);
        }
        float mean = s * (1.0f / 128.0f);
        float var  = ss * (1.0f / 128.0f) - mean * mean;
        float rstd = rsqrtf(var + 1e-5f);
        size_t base = ((size_t)row * KNB + e) * 128;
        outE[base + lane]      = (v0 - mean) * rstd * ln_g[lane]      + ln_b[lane];
        outE[base + lane + 32] = (v1 - mean) * rstd * ln_g[lane + 32] + ln_b[lane + 32];
        outE[base + lane + 64] = (v2 - mean) * rstd * ln_g[lane + 64] + ln_b[lane + 64];
        outE[base + lane + 96] = (v3 - mean) * rstd * ln_g[lane + 96] + ln_b[lane + 96];
    }
}

// ---------------------------------------------------------------------------
extern "C" void kernel_launch(void* const* d_in, const int* in_sizes, int n_in,
                              void* d_out, int out_size) {
    const float* X     = (const float*)d_in[0];
    const int*   S     = (const int*)d_in[2];
    const int*   ridx  = (const int*)d_in[3];
    const int*   table = (const int*)d_in[5];
    const float* W_pos = (const float*)d_in[6];
    const float* b_pos = (const float*)d_in[7];
    const float* W_e   = (const float*)d_in[8];
    const float* ln_g  = (const float*)d_in[9];
    const float* ln_b  = (const float*)d_in[10];
    float* out = (float*)d_out;

    const size_t E_elems = (size_t)NRES * KNB * NOUT;
    int write_idx = (out_size >= (int)(E_elems + (size_t)NRES * KNB)) ? 1 : 0;

    build_xall_kernel<<<(NRES + 255) / 256, 256>>>(X, S, table);
    prep_w_kernel<<<(NKS * 16 * 32 + 255) / 256, 256>>>(W_e);
    topk_kernel<<<NRES, 256>>>(out + E_elems, write_idx);

    cudaFuncSetAttribute(edge_kernel, cudaFuncAttributeMaxDynamicSharedMemorySize, SMB_TOT);
    edge_kernel<<<NRES, 256, SMB_TOT>>>(ridx, W_pos, b_pos, ln_g, ln_b, out);
}